// round 2
// baseline (speedup 1.0000x reference)
#include <cuda_runtime.h>
#include <cuda_bf16.h>

#define IMG_W 512
#define IMG_H 512
#define ROWS_PER_BLOCK 32
#define NTHREADS 128   // 4 warps; each warp owns 128 contiguous columns

// 3x3 local variance, stride 1, zero pad 1, divisor 9.
// One block = one (b,c) plane x 32-row band. Warp-autonomous: no smem, no
// barriers. Halo columns come from warp shuffles; the two warp-boundary
// elements come from divergent scalar LDGs (lane 0 / lane 31 only).
__global__ __launch_bounds__(NTHREADS)
void ChannelwiseVariance_85091892068508_kernel(const float* __restrict__ x,
                                               float* __restrict__ out)
{
    const int tid   = threadIdx.x;
    const int lane  = tid & 31;
    const int warp  = tid >> 5;
    const int col   = warp * 128 + lane * 4;       // first of 4 owned columns
    const int y0    = blockIdx.x * ROWS_PER_BLOCK; // first output row of band
    const size_t plane = (size_t)blockIdx.y * (size_t)(IMG_H * IMG_W);

    const bool has_left  = (col != 0);             // col-1 exists in image
    const bool has_right = (col + 4 != IMG_W);     // col+4 exists in image
    const float inv9 = 1.0f / 9.0f;

    // Rolling horizontal 3-sums for the last 3 input rows (v and v^2).
    float4 hv0, hv1, hv2;
    float4 hq0, hq1, hq2;

    #pragma unroll 2
    for (int it = 0; it < ROWS_PER_BLOCK + 2; ++it) {
        const int r = y0 - 1 + it;                 // input row (-1 .. IMG_H)
        const bool rvalid = (r >= 0) && (r < IMG_H);
        const size_t rowoff = plane + (size_t)r * IMG_W;

        float4 v = make_float4(0.f, 0.f, 0.f, 0.f);
        if (rvalid) {
            v = *reinterpret_cast<const float4*>(x + rowoff + col);
        }

        // Halo via shuffle; warp-boundary lanes fetch the single missing
        // element directly from global (zero at image edge / invalid row).
        float l  = __shfl_up_sync(0xffffffffu, v.w, 1);
        float rr = __shfl_down_sync(0xffffffffu, v.x, 1);
        if (lane == 0) {
            l = (rvalid && has_left) ? x[rowoff + col - 1] : 0.0f;
        }
        if (lane == 31) {
            rr = (rvalid && has_right) ? x[rowoff + col + 4] : 0.0f;
        }

        // Horizontal 3-sums for the 4 owned output columns.
        float4 hv, hq;
        hv.x = l   + v.x + v.y;
        hv.y = v.x + v.y + v.z;
        hv.z = v.y + v.z + v.w;
        hv.w = v.z + v.w + rr;

        const float lq = l * l, aq = v.x * v.x, bq = v.y * v.y,
                    cq = v.z * v.z, dq = v.w * v.w, rq = rr * rr;
        hq.x = lq + aq + bq;
        hq.y = aq + bq + cq;
        hq.z = bq + cq + dq;
        hq.w = cq + dq + rq;

        // Shift rolling window.
        hv0 = hv1; hv1 = hv2; hv2 = hv;
        hq0 = hq1; hq1 = hq2; hq2 = hq;

        if (it >= 2) {
            const int y = r - 1;                   // output row
            float4 S1, S2, o;
            S1.x = hv0.x + hv1.x + hv2.x;  S2.x = hq0.x + hq1.x + hq2.x;
            S1.y = hv0.y + hv1.y + hv2.y;  S2.y = hq0.y + hq1.y + hq2.y;
            S1.z = hv0.z + hv1.z + hv2.z;  S2.z = hq0.z + hq1.z + hq2.z;
            S1.w = hv0.w + hv1.w + hv2.w;  S2.w = hq0.w + hq1.w + hq2.w;

            const float m0 = S1.x * inv9, m1 = S1.y * inv9,
                        m2 = S1.z * inv9, m3 = S1.w * inv9;
            o.x = fmaf(-m0, m0, S2.x * inv9);
            o.y = fmaf(-m1, m1, S2.y * inv9);
            o.z = fmaf(-m2, m2, S2.z * inv9);
            o.w = fmaf(-m3, m3, S2.w * inv9);

            *reinterpret_cast<float4*>(out + plane + (size_t)y * IMG_W + col) = o;
        }
    }
}

extern "C" void kernel_launch(void* const* d_in, const int* in_sizes, int n_in,
                              void* d_out, int out_size)
{
    const float* x = (const float*)d_in[0];
    float* out = (float*)d_out;

    const int planes = in_sizes[0] / (IMG_H * IMG_W);   // 8*32 = 256
    dim3 grid(IMG_H / ROWS_PER_BLOCK, planes);          // (16, 256)
    dim3 block(NTHREADS);
    ChannelwiseVariance_85091892068508_kernel<<<grid, block>>>(x, out);
}

// round 3
// speedup vs baseline: 1.1686x; 1.1686x over previous
#include <cuda_runtime.h>
#include <cuda_bf16.h>

#define IMG_W 512
#define IMG_H 512
#define SUBROWS 32          // rows per warp strip
#define NTHREADS 128        // 4 warps: (colhalf = w&1, subband = w>>1)

// 3x3 local variance, stride 1, zero pad 1, divisor 9.
// Warp-autonomous: each lane owns 8 contiguous columns (2x LDG.128 per row ->
// MLP 2). Keep raw 3-row value history; vertical sums first, squares
// recomputed, horizontal 3-sum via warp shuffles. Lanes 0/31 keep a rolling
// scalar history for the warp-boundary column.
__global__ __launch_bounds__(NTHREADS, 6)
void ChannelwiseVariance_85091892068508_kernel(const float* __restrict__ x,
                                               float* __restrict__ out)
{
    const int tid  = threadIdx.x;
    const int lane = tid & 31;
    const int w    = tid >> 5;
    const int colhalf = w & 1;
    const int sub     = w >> 1;
    const int col  = colhalf * 256 + lane * 8;     // first of 8 owned columns
    const int y0   = blockIdx.x * (2 * SUBROWS) + sub * SUBROWS;
    const size_t plane = (size_t)blockIdx.y * (size_t)(IMG_H * IMG_W);

    const bool has_left  = (col != 0);
    const bool has_right = (col + 8 != IMG_W);
    const float inv9 = 1.0f / 9.0f;

    float v[3][8];            // raw value history, 3 rows x 8 cols
    float lx[3], rx[3];       // boundary-column history (lanes 0 / 31)
    #pragma unroll
    for (int j = 0; j < 8; ++j) { v[0][j] = 0.f; v[1][j] = 0.f; v[2][j] = 0.f; }
    lx[0] = lx[1] = lx[2] = 0.f;
    rx[0] = rx[1] = rx[2] = 0.f;

    #pragma unroll 2
    for (int it = 0; it < SUBROWS + 2; ++it) {
        const int r = y0 - 1 + it;
        const bool rvalid = (r >= 0) && (r < IMG_H);
        const size_t rowoff = plane + (size_t)r * IMG_W;

        float4 va = make_float4(0.f, 0.f, 0.f, 0.f);
        float4 vb = make_float4(0.f, 0.f, 0.f, 0.f);
        float lxn = 0.f, rxn = 0.f;
        if (rvalid) {
            va = *reinterpret_cast<const float4*>(x + rowoff + col);
            vb = *reinterpret_cast<const float4*>(x + rowoff + col + 4);
        }
        if (lane == 0 && rvalid && has_left)   lxn = x[rowoff + col - 1];
        if (lane == 31 && rvalid && has_right) rxn = x[rowoff + col + 8];

        // push history
        #pragma unroll
        for (int j = 0; j < 8; ++j) { v[0][j] = v[1][j]; v[1][j] = v[2][j]; }
        v[2][0] = va.x; v[2][1] = va.y; v[2][2] = va.z; v[2][3] = va.w;
        v[2][4] = vb.x; v[2][5] = vb.y; v[2][6] = vb.z; v[2][7] = vb.w;
        lx[0] = lx[1]; lx[1] = lx[2]; lx[2] = lxn;
        rx[0] = rx[1]; rx[1] = rx[2]; rx[2] = rxn;

        if (it >= 2) {
            // vertical 3-sums of v and v^2 per owned column
            float sv[10], sq[10];   // [0]=left halo, [1..8]=owned, [9]=right halo
            #pragma unroll
            for (int j = 0; j < 8; ++j) {
                const float a = v[0][j], b = v[1][j], c = v[2][j];
                sv[j + 1] = a + b + c;
                sq[j + 1] = fmaf(a, a, fmaf(b, b, c * c));
            }
            float sv_l = __shfl_up_sync(0xffffffffu, sv[8], 1);
            float sq_l = __shfl_up_sync(0xffffffffu, sq[8], 1);
            float sv_r = __shfl_down_sync(0xffffffffu, sv[1], 1);
            float sq_r = __shfl_down_sync(0xffffffffu, sq[1], 1);
            if (lane == 0) {       // zero history when !has_left
                sv_l = lx[0] + lx[1] + lx[2];
                sq_l = fmaf(lx[0], lx[0], fmaf(lx[1], lx[1], lx[2] * lx[2]));
            }
            if (lane == 31) {
                sv_r = rx[0] + rx[1] + rx[2];
                sq_r = fmaf(rx[0], rx[0], fmaf(rx[1], rx[1], rx[2] * rx[2]));
            }
            sv[0] = sv_l; sq[0] = sq_l;
            sv[9] = sv_r; sq[9] = sq_r;

            float o[8];
            #pragma unroll
            for (int j = 0; j < 8; ++j) {
                const float S1 = sv[j] + sv[j + 1] + sv[j + 2];
                const float S2 = sq[j] + sq[j + 1] + sq[j + 2];
                const float m = S1 * inv9;
                o[j] = fmaf(-m, m, S2 * inv9);
            }

            const int y = r - 1;
            float* op = out + plane + (size_t)y * IMG_W + col;
            __stcs(reinterpret_cast<float4*>(op),
                   make_float4(o[0], o[1], o[2], o[3]));
            __stcs(reinterpret_cast<float4*>(op + 4),
                   make_float4(o[4], o[5], o[6], o[7]));
        }
    }
}

extern "C" void kernel_launch(void* const* d_in, const int* in_sizes, int n_in,
                              void* d_out, int out_size)
{
    const float* x = (const float*)d_in[0];
    float* out = (float*)d_out;

    const int planes = in_sizes[0] / (IMG_H * IMG_W);   // 8*32 = 256
    dim3 grid(IMG_H / (2 * SUBROWS), planes);           // (8, 256)
    dim3 block(NTHREADS);
    ChannelwiseVariance_85091892068508_kernel<<<grid, block>>>(x, out);
}

// round 4
// speedup vs baseline: 1.2094x; 1.0350x over previous
#include <cuda_runtime.h>
#include <cuda_bf16.h>

#define IMG_W 512
#define IMG_H 512
#define SUBROWS 64          // rows per warp strip
#define NTHREADS 128        // 4 warps: (colhalf = w&1, subband = w>>1)

// 3x3 local variance, stride 1, zero pad 1, divisor 9.
// Warp-autonomous: each lane owns 8 contiguous columns (2x LDG.128 per row).
// Rolling state per lane: previous-row values vp[8], pair sums p[8] (last two
// rows) and pair square-sums q[8]. Vertical 3-sum = p + current, then
// horizontal 3-sum via warp shuffles; warp-boundary column kept as scalar
// rolling state in lanes 0/31.
__global__ __launch_bounds__(NTHREADS, 8)
void ChannelwiseVariance_85091892068508_kernel(const float* __restrict__ x,
                                               float* __restrict__ out)
{
    const int tid  = threadIdx.x;
    const int lane = tid & 31;
    const int w    = tid >> 5;
    const int colhalf = w & 1;
    const int sub     = w >> 1;
    const int col  = colhalf * 256 + lane * 8;     // first of 8 owned columns
    const int y0   = blockIdx.x * (2 * SUBROWS) + sub * SUBROWS;
    const size_t plane = (size_t)blockIdx.y * (size_t)(IMG_H * IMG_W);

    const bool has_left  = (col != 0);
    const bool has_right = (col + 8 != IMG_W);
    const float inv9 = 1.0f / 9.0f;

    float vp[8], p[8], q[8];
    #pragma unroll
    for (int j = 0; j < 8; ++j) { vp[j] = 0.f; p[j] = 0.f; q[j] = 0.f; }
    // boundary-column rolling state (lanes 0 / 31)
    float lxp = 0.f, lp = 0.f, lq = 0.f;
    float rxp = 0.f, rp = 0.f, rq = 0.f;

    #pragma unroll 2
    for (int it = 0; it < SUBROWS + 2; ++it) {
        const int r = y0 - 1 + it;
        const bool rvalid = (r >= 0) && (r < IMG_H);
        const size_t rowoff = plane + (size_t)r * IMG_W;

        float4 va = make_float4(0.f, 0.f, 0.f, 0.f);
        float4 vb = make_float4(0.f, 0.f, 0.f, 0.f);
        float lxn = 0.f, rxn = 0.f;
        if (rvalid) {
            va = *reinterpret_cast<const float4*>(x + rowoff + col);
            vb = *reinterpret_cast<const float4*>(x + rowoff + col + 4);
        }
        if (lane == 0 && rvalid && has_left)   lxn = x[rowoff + col - 1];
        if (lane == 31 && rvalid && has_right) rxn = x[rowoff + col + 8];

        float vc[8];
        vc[0] = va.x; vc[1] = va.y; vc[2] = va.z; vc[3] = va.w;
        vc[4] = vb.x; vc[5] = vb.y; vc[6] = vb.z; vc[7] = vb.w;

        // Vertical 3-sums for output row r-1, then roll state forward.
        float S1[8], S2[8];
        #pragma unroll
        for (int j = 0; j < 8; ++j) {
            const float sq = vc[j] * vc[j];
            S1[j] = p[j] + vc[j];
            S2[j] = q[j] + sq;
            p[j]  = vp[j] + vc[j];
            q[j]  = fmaf(vp[j], vp[j], sq);
            vp[j] = vc[j];
        }
        // Boundary scalars (live in lanes 0 / 31).
        const float lsq = lxn * lxn, rsq = rxn * rxn;
        const float lS1 = lp + lxn, lS2 = lq + lsq;
        const float rS1 = rp + rxn, rS2 = rq + rsq;
        lp = lxp + lxn; lq = fmaf(lxp, lxp, lsq); lxp = lxn;
        rp = rxp + rxn; rq = fmaf(rxp, rxp, rsq); rxp = rxn;

        if (it >= 2) {
            // Horizontal halo of vertical sums via shuffles.
            float sv_l = __shfl_up_sync(0xffffffffu, S1[7], 1);
            float sq_l = __shfl_up_sync(0xffffffffu, S2[7], 1);
            float sv_r = __shfl_down_sync(0xffffffffu, S1[0], 1);
            float sq_r = __shfl_down_sync(0xffffffffu, S2[0], 1);
            if (lane == 0)  { sv_l = lS1; sq_l = lS2; }
            if (lane == 31) { sv_r = rS1; sq_r = rS2; }

            float o[8];
            {
                float t1 = sv_l + S1[0] + S1[1];
                float t2 = sq_l + S2[0] + S2[1];
                float m = t1 * inv9; o[0] = fmaf(-m, m, t2 * inv9);
            }
            #pragma unroll
            for (int j = 1; j < 7; ++j) {
                float t1 = S1[j - 1] + S1[j] + S1[j + 1];
                float t2 = S2[j - 1] + S2[j] + S2[j + 1];
                float m = t1 * inv9; o[j] = fmaf(-m, m, t2 * inv9);
            }
            {
                float t1 = S1[6] + S1[7] + sv_r;
                float t2 = S2[6] + S2[7] + sq_r;
                float m = t1 * inv9; o[7] = fmaf(-m, m, t2 * inv9);
            }

            const int y = r - 1;
            float* op = out + plane + (size_t)y * IMG_W + col;
            __stcs(reinterpret_cast<float4*>(op),
                   make_float4(o[0], o[1], o[2], o[3]));
            __stcs(reinterpret_cast<float4*>(op + 4),
                   make_float4(o[4], o[5], o[6], o[7]));
        }
    }
}

extern "C" void kernel_launch(void* const* d_in, const int* in_sizes, int n_in,
                              void* d_out, int out_size)
{
    const float* x = (const float*)d_in[0];
    float* out = (float*)d_out;

    const int planes = in_sizes[0] / (IMG_H * IMG_W);   // 8*32 = 256
    dim3 grid(IMG_H / (2 * SUBROWS), planes);           // (4, 256) = 1024 blocks
    dim3 block(NTHREADS);
    ChannelwiseVariance_85091892068508_kernel<<<grid, block>>>(x, out);
}